// round 15
// baseline (speedup 1.0000x reference)
#include <cuda_runtime.h>
#include <cuda_fp16.h>
#include <math.h>
#include <stdint.h>

// Legacy mma.sync path (tcgen05 blocked by sm_103 ptxas target).
// R12: main term Ah*Bh in fp32-acc HMMA (rt~16); correction Al*Bh in
// fp16-acc HMMA (rt~8 if 2x rate) -- correction is 2^-11-scale so fp16
// accumulation error is ~1e-6 end-to-end. LN switched to single-pass.

// ---------------- constants ----------------
#define NB      64
#define NPATCH  16
#define PATCH   32
#define DMODEL  1024
#define NH      16
#define HDIM    64
#define NDFF    4096
#define NLAYER  8
#define CMAX    20
#define T1      1024
#define T2      256
#define EPSF    1e-6f

// ---------------- device scratch ----------------
__device__ float g_normed[T1 * PATCH];
__device__ float g_anorm [T2 * PATCH];
__device__ float g_ctxmu [NB * NPATCH];
__device__ float g_ctxsg [NB * NPATCH];
__device__ float g_nmu   [NB * 4];
__device__ float g_nsg   [NB * 4];
__device__ int   g_ispos [32];
__device__ float g_hdd [T1 * DMODEL];
__device__ float g_xn  [T1 * DMODEL];
__device__ float g_qkv [T1 * 3 * DMODEL];
__device__ float g_Kc  [NLAYER * NB * CMAX * DMODEL];
__device__ float g_Vc  [NLAYER * NB * CMAX * DMODEL];
__device__ float g_no1 [NB * 128];
__device__ float g_no2 [NB * 128];
__device__ float g_last[NB * 128];
__device__ float g_Wsel[1024 * 128];

// fp16 hi/lo activation buffers (A side of GEMMs)
__device__ __half g_xnh [T1 * DMODEL], g_xnl [T1 * DMODEL];
__device__ __half g_atth[T1 * DMODEL], g_attl[T1 * DMODEL];
__device__ __half g_h1h [T1 * NDFF],   g_h1l [T1 * NDFF];

// transposed fp16 weights (hi only): [L][N][K]
__device__ __half g_Wqkvh[(size_t)NLAYER * 3072 * 1024];
__device__ __half g_Woh [(size_t)NLAYER * 1024 * 1024];
__device__ __half g_W1h [(size_t)NLAYER * 4096 * 1024];
__device__ __half g_W2h [(size_t)NLAYER * 1024 * 4096];

// ---------------- helpers ----------------
__device__ __forceinline__ float warpSum(float v) {
#pragma unroll
    for (int o = 16; o; o >>= 1) v += __shfl_xor_sync(0xffffffffu, v, o);
    return v;
}

__device__ __forceinline__ float gelu_tanh(float x) {
    float x3 = x * x * x;
    return 0.5f * x * (1.0f + tanhf(0.7978845608028654f * (x + 0.044715f * x3)));
}

__device__ __forceinline__ void split_fp16(float v, __half& h, __half& l) {
    h = __float2half_rn(v);
    l = __float2half_rn(v - __half2float(h));
}

// ---------------- weight transpose + fp16 convert (hi only) ----------------
__global__ void convT_kernel(const float* __restrict__ W,
                             __half* __restrict__ Th, int K, int N) {
    __shared__ float t[32][33];
    int l = blockIdx.z;
    const float* Wl = W + (size_t)l * K * N;
    __half* Thl = Th + (size_t)l * K * N;
    int n0 = blockIdx.x * 32, k0 = blockIdx.y * 32;
#pragma unroll
    for (int i = 0; i < 4; i++)
        t[threadIdx.y + 8 * i][threadIdx.x] =
            Wl[(size_t)(k0 + threadIdx.y + 8 * i) * N + n0 + threadIdx.x];
    __syncthreads();
#pragma unroll
    for (int i = 0; i < 4; i++) {
        int n = threadIdx.y + 8 * i;
        Thl[(size_t)(n0 + n) * K + k0 + threadIdx.x] = __float2half_rn(t[threadIdx.x][n]);
    }
}

// ---------------- Wout channel-5 column extraction ----------------
__global__ void wsel_kernel(const float* __restrict__ Wout) {
    int i = blockIdx.x * blockDim.x + threadIdx.x;
    int k = i >> 7, j = i & 127;
    g_Wsel[i] = Wout[k * 1280 + 5 + 10 * j];
}

__global__ void wout_kernel(const float* __restrict__ xn, float* __restrict__ outv,
                            int selStart, int selStep) {
    __shared__ float sx[8][1024];
    int j = threadIdx.x;
    int b0 = blockIdx.x * 8;
#pragma unroll
    for (int i = 0; i < 8; i++) {
        int row = selStart + (b0 + i) * selStep;
        for (int c = j; c < 1024; c += 128) sx[i][c] = xn[(size_t)row * 1024 + c];
    }
    __syncthreads();
    float acc[8] = {};
    for (int k = 0; k < 1024; k++) {
        float w = g_Wsel[k * 128 + j];
#pragma unroll
        for (int i = 0; i < 8; i++) acc[i] += sx[i][k] * w;
    }
#pragma unroll
    for (int i = 0; i < 8; i++) outv[(b0 + i) * 128 + j] = acc[i];
}

// ---------------- running stats ----------------
__global__ void stats_kernel(const float* __restrict__ x) {
    int b = blockIdx.x, lane = threadIdx.x;
    const float* xb = x + (size_t)(b & 31) * 512;
    float sign = (b < 32) ? 1.f : -1.f;
    if (b < 32) {
        bool ok = true;
        for (int i = lane; i < 512; i += 32) ok = ok && (xb[i] >= 0.f);
        unsigned bal = __ballot_sync(0xffffffffu, ok);
        if (lane == 0) g_ispos[b] = (bal == 0xffffffffu) ? 1 : 0;
    }
    float n = 0.f, mu = 0.f, sg = 0.f;
    for (int p = 0; p < NPATCH; p++) {
        float v = sign * xb[p * PATCH + lane];
        float s = warpSum(v);
        float nn = n + 32.f;
        float nmu = (n * mu + s) / nn;
        float m2 = n * sg * sg + warpSum((v - mu) * (v - nmu));
        float nsg = sqrtf(fmaxf(m2 / nn, 1e-12f));
        n = nn; mu = nmu; sg = nsg;
        if (lane == 0) { g_ctxmu[b * NPATCH + p] = mu; g_ctxsg[b * NPATCH + p] = sg; }
        g_normed[(b * NPATCH + p) * PATCH + lane] = (v - mu) / (sg + EPSF);
    }
}

// fused: revin(last prefill output) -> g_last, then AR Welford stats -> g_anorm
__global__ void revin_ar_stats_kernel() {
    int b = blockIdx.x, lane = threadIdx.x;
    float mu0 = g_ctxmu[b * NPATCH + 15], sg0 = g_ctxsg[b * NPATCH + 15];
    float scale = sg0 + EPSF;
    float n = 512.f, mu = mu0, sg = sg0;
    for (int p = 0; p < 4; p++) {
        float v = g_no1[b * 128 + p * 32 + lane] * scale + mu0;
        g_last[b * 128 + p * 32 + lane] = v;
        float s = warpSum(v);
        float nn = n + 32.f;
        float nmu = (n * mu + s) / nn;
        float m2 = n * sg * sg + warpSum((v - mu) * (v - nmu));
        float ns = sqrtf(fmaxf(m2 / nn, 1e-12f));
        n = nn; mu = nmu; sg = ns;
        if (lane == 0) { g_nmu[b * 4 + p] = mu; g_nsg[b * 4 + p] = ns; }
        g_anorm[(b * 4 + p) * 32 + lane] = (v - mu) / (sg + EPSF);
    }
}

// ---------------- layernorms (single-pass: E[x], E[x^2]) ----------------
__global__ void ln_kernel(const float* __restrict__ in, const float* __restrict__ sc,
                          float* __restrict__ out) {
    __shared__ float row[DMODEL];
    __shared__ float red1[8], red2[8];
    __shared__ float s_mean, s_inv;
    int r = blockIdx.x, tid = threadIdx.x;
    const float* xr = in + (size_t)r * DMODEL;
    float s1 = 0.f, s2 = 0.f;
    for (int c = tid; c < DMODEL; c += 256) {
        float v = xr[c]; row[c] = v; s1 += v; s2 += v * v;
    }
    s1 = warpSum(s1); s2 = warpSum(s2);
    if ((tid & 31) == 0) { red1[tid >> 5] = s1; red2[tid >> 5] = s2; }
    __syncthreads();
    if (tid < 8) {
        float t1 = red1[tid], t2 = red2[tid];
#pragma unroll
        for (int o = 4; o; o >>= 1) {
            t1 += __shfl_xor_sync(0xffu, t1, o);
            t2 += __shfl_xor_sync(0xffu, t2, o);
        }
        if (tid == 0) {
            float m = t1 / (float)DMODEL;
            s_mean = m;
            s_inv = rsqrtf(fmaxf(t2 / (float)DMODEL - m * m, 0.f) + EPSF);
        }
    }
    __syncthreads();
    float m = s_mean, inv = s_inv;
    for (int c = tid; c < DMODEL; c += 256)
        out[(size_t)r * DMODEL + c] = (row[c] - m) * inv * sc[c];
}

__global__ void ln_fp16_kernel(const float* __restrict__ in, const float* __restrict__ sc,
                               __half* __restrict__ oh, __half* __restrict__ ol) {
    __shared__ float row[DMODEL];
    __shared__ float red1[8], red2[8];
    __shared__ float s_mean, s_inv;
    int r = blockIdx.x, tid = threadIdx.x;
    const float* xr = in + (size_t)r * DMODEL;
    float s1 = 0.f, s2 = 0.f;
    for (int c = tid; c < DMODEL; c += 256) {
        float v = xr[c]; row[c] = v; s1 += v; s2 += v * v;
    }
    s1 = warpSum(s1); s2 = warpSum(s2);
    if ((tid & 31) == 0) { red1[tid >> 5] = s1; red2[tid >> 5] = s2; }
    __syncthreads();
    if (tid < 8) {
        float t1 = red1[tid], t2 = red2[tid];
#pragma unroll
        for (int o = 4; o; o >>= 1) {
            t1 += __shfl_xor_sync(0xffu, t1, o);
            t2 += __shfl_xor_sync(0xffu, t2, o);
        }
        if (tid == 0) {
            float m = t1 / (float)DMODEL;
            s_mean = m;
            s_inv = rsqrtf(fmaxf(t2 / (float)DMODEL - m * m, 0.f) + EPSF);
        }
    }
    __syncthreads();
    float m = s_mean, inv = s_inv;
    for (int c = tid; c < DMODEL; c += 256) {
        float v = (row[c] - m) * inv * sc[c];
        __half h, lo; split_fp16(v, h, lo);
        oh[(size_t)r * DMODEL + c] = h;
        ol[(size_t)r * DMODEL + c] = lo;
    }
}

// ================= fp16 2-term GEMM: fp32-acc main + fp16-acc correction ====
#define MMA_F16F32(d, a, b)                                                     \
    asm volatile(                                                               \
        "mma.sync.aligned.m16n8k16.row.col.f32.f16.f16.f32 "                    \
        "{%0,%1,%2,%3},{%4,%5,%6,%7},{%8,%9},{%0,%1,%2,%3};"                    \
        : "+f"((d)[0]), "+f"((d)[1]), "+f"((d)[2]), "+f"((d)[3])                \
        : "r"((a)[0]), "r"((a)[1]), "r"((a)[2]), "r"((a)[3]),                   \
          "r"((b)[0]), "r"((b)[1]))

#define MMA_F16F16(d, a, b)                                                     \
    asm volatile(                                                               \
        "mma.sync.aligned.m16n8k16.row.col.f16.f16.f16.f16 "                    \
        "{%0,%1},{%2,%3,%4,%5},{%6,%7},{%0,%1};"                                \
        : "+r"((d)[0]), "+r"((d)[1])                                            \
        : "r"((a)[0]), "r"((a)[1]), "r"((a)[2]), "r"((a)[3]),                   \
          "r"((b)[0]), "r"((b)[1]))

#define LDSM4(r0, r1, r2, r3, addr)                                             \
    asm volatile("ldmatrix.sync.aligned.m8n8.x4.shared.b16 {%0,%1,%2,%3},[%4];" \
        : "=r"(r0), "=r"(r1), "=r"(r2), "=r"(r3) : "r"(addr))

#define CP16(dst, src)                                                          \
    asm volatile("cp.async.cg.shared.global [%0], [%1], 16;" ::                 \
                 "r"(dst), "l"(src) : "memory")

#define CPCOMMIT() asm volatile("cp.async.commit_group;" ::: "memory")

// stage layout: [Ah: BM rows x 128B][Al: BM rows x 128B][Bh: BN rows x 128B]
template<int BM, int BN>
__device__ __forceinline__ void load_stage_fn(uint32_t base, int tid,
        const __half* __restrict__ Ah, const __half* __restrict__ Al,
        const __half* __restrict__ Bh, int K, int kt) {
#pragma unroll
    for (int i = 0; i < BM * 8 / 256; i++) {
        int cid = tid + i * 256;
        int r = cid >> 3, c = cid & 7;
        CP16(base + r * 128 + ((c ^ (r & 7)) << 4),
             Ah + (size_t)r * K + kt * 64 + c * 8);
    }
#pragma unroll
    for (int i = 0; i < BM * 8 / 256; i++) {
        int cid = tid + i * 256;
        int r = cid >> 3, c = cid & 7;
        CP16(base + BM * 128 + r * 128 + ((c ^ (r & 7)) << 4),
             Al + (size_t)r * K + kt * 64 + c * 8);
    }
#pragma unroll
    for (int i = 0; i < BN * 8 / 256; i++) {
        int cid = tid + i * 256;
        int r = cid >> 3, c = cid & 7;
        CP16(base + 2 * BM * 128 + r * 128 + ((c ^ (r & 7)) << 4),
             Bh + (size_t)r * K + kt * 64 + c * 8);
    }
}

template<int BM, int BN>
__global__ void __launch_bounds__(256, (BN == 128) ? 2 : 3)
fp16_gemm_kernel(
        const __half* __restrict__ Ah, const __half* __restrict__ Al,
        const __half* __restrict__ Bh,
        float* __restrict__ C, __half* __restrict__ Chi, __half* __restrict__ Clo,
        int M, int N, int K, int flags) {
    extern __shared__ __align__(128) char smem[];
    constexpr int ASTAGE = BM * 128;
    constexpr int STAGE  = (2 * BM + BN) * 128;
    uint32_t smBase = (uint32_t)__cvta_generic_to_shared(smem);

    const int tid  = threadIdx.x;
    const int lane = tid & 31;
    const int gid  = lane >> 2;
    const int tig  = lane & 3;
    const int warp = tid >> 5;
    constexpr int MT = (BM / 2) / 16;
    constexpr int NT = (BN / 4) / 8;
    const int wm = warp & 1, wn = warp >> 1;
    const int mBase = wm * (BM / 2);
    const int nBase = wn * (BN / 4);
    const int blockRow = blockIdx.y * BM;
    const int blockCol = blockIdx.x * BN;

    const __half* Ah0 = Ah + (size_t)blockRow * K;
    const __half* Al0 = Al + (size_t)blockRow * K;
    const __half* Bh0 = Bh + (size_t)blockCol * K;

    float acc[MT][NT][4];
    uint32_t accLo[MT][NT][2];                 // fp16x2 accumulators (lo term)
#pragma unroll
    for (int i = 0; i < MT; i++)
#pragma unroll
        for (int j = 0; j < NT; j++) {
#pragma unroll
            for (int q = 0; q < 4; q++) acc[i][j][q] = 0.f;
            accLo[i][j][0] = 0u; accLo[i][j][1] = 0u;
        }

    const int ktiles = K / 64;
    const int ksl = ktiles / gridDim.z;
    const int kt0 = ksl * blockIdx.z;

    const int arow = (lane & 7) + ((lane >> 3) & 1) * 8;
    const int acsel = lane >> 4;
    const int nrow = lane & 7;
    const int bcsel = (lane >> 3) & 1;
    const int ntsel = lane >> 4;

    load_stage_fn<BM, BN>(smBase, tid, Ah0, Al0, Bh0, K, kt0);
    CPCOMMIT();
    load_stage_fn<BM, BN>(smBase + STAGE, tid, Ah0, Al0, Bh0, K, kt0 + 1);
    CPCOMMIT();

    for (int ktl = 0; ktl < ksl; ktl++) {
        asm volatile("cp.async.wait_group 1;" ::: "memory");
        __syncthreads();
        if (ktl + 2 < ksl)
            load_stage_fn<BM, BN>(smBase + ((ktl + 2) % 3) * STAGE, tid,
                                  Ah0, Al0, Bh0, K, kt0 + ktl + 2);
        CPCOMMIT();

        uint32_t AhA = smBase + (ktl % 3) * STAGE;
        uint32_t AlA = AhA + ASTAGE;
        uint32_t BhA = AhA + 2 * ASTAGE;
#pragma unroll
        for (int s = 0; s < 4; s++) {
            const int ck = 2 * s;
            uint32_t bh[NT][2];
#pragma unroll
            for (int np = 0; np < NT / 2; np++) {
                int nt0 = np * 2;
                int r = nBase + (nt0 + ntsel) * 8 + nrow;
                LDSM4(bh[nt0][0], bh[nt0][1], bh[nt0 + 1][0], bh[nt0 + 1][1],
                      BhA + r * 128 + (((ck + bcsel) ^ (r & 7)) << 4));
            }
#pragma unroll
            for (int mt = 0; mt < MT; mt++) {
                uint32_t ah[4], al[4];
                int r = mBase + mt * 16 + arow;
                int xo = ((ck + acsel) ^ (r & 7)) << 4;
                LDSM4(ah[0], ah[1], ah[2], ah[3], AhA + r * 128 + xo);
                LDSM4(al[0], al[1], al[2], al[3], AlA + r * 128 + xo);
#pragma unroll
                for (int nt = 0; nt < NT; nt++) MMA_F16F32(acc[mt][nt], ah, bh[nt]);
#pragma unroll
                for (int nt = 0; nt < NT; nt++) MMA_F16F16(accLo[mt][nt], al, bh[nt]);
            }
        }
    }

    // epilogue: merge fp16 lo-accumulators into fp32 accs, then write
    const bool multiZ = (gridDim.z > 1);
#pragma unroll
    for (int mt = 0; mt < MT; mt++) {
#pragma unroll
        for (int nt = 0; nt < NT; nt++) {
            float* a = acc[mt][nt];
            __half2 lo0 = *(__half2*)&accLo[mt][nt][0];
            __half2 lo1 = *(__half2*)&accLo[mt][nt][1];
            a[0] += __half2float(lo0.x); a[1] += __half2float(lo0.y);
            a[2] += __half2float(lo1.x); a[3] += __half2float(lo1.y);
            int col = blockCol + nBase + nt * 8 + tig * 2;
#pragma unroll
            for (int hh = 0; hh < 2; hh++) {
                int row = blockRow + mBase + mt * 16 + gid + hh * 8;
                size_t o = (size_t)row * N + col;
                float v0 = a[hh * 2 + 0], v1 = a[hh * 2 + 1];
                if (flags == 2) {
                    float g0 = gelu_tanh(v0), g1 = gelu_tanh(v1);
                    __half h0, l0, h1, l1;
                    split_fp16(g0, h0, l0); split_fp16(g1, h1, l1);
                    Chi[o] = h0; Clo[o] = l0; Chi[o + 1] = h1; Clo[o + 1] = l1;
                } else if (flags == 1) {
                    if (multiZ) { atomicAdd(&C[o], v0); atomicAdd(&C[o + 1], v1); }
                    else        { C[o] += v0; C[o + 1] += v1; }
                } else {
                    C[o] = v0; C[o + 1] = v1;
                }
            }
        }
    }
}

static void launch_fp16(const __half* Ah, const __half* Al, const __half* Bh,
                        float* C, __half* Chi, __half* Clo,
                        int M, int N, int K, int flags) {
    if (M >= 1024 && N >= 2048) {            // QKV/W1 prefill: <64,128>
        constexpr int SMB = 3 * (2 * 64 + 128) * 128;
        cudaFuncSetAttribute(fp16_gemm_kernel<64, 128>,
                             cudaFuncAttributeMaxDynamicSharedMemorySize, SMB);
        dim3 grid(N / 128, M / 64);
        fp16_gemm_kernel<64, 128><<<grid, 256, SMB>>>(Ah, Al, Bh, C, Chi, Clo,
                                                      M, N, K, flags);
    } else {                                  // everything else: <64,64>
        constexpr int SMB = 3 * (2 * 64 + 64) * 128;
        cudaFuncSetAttribute(fp16_gemm_kernel<64, 64>,
                             cudaFuncAttributeMaxDynamicSharedMemorySize, SMB);
        int ks = (flags == 1 && M < 1024 && N <= 1024) ? 4 : 1;
        dim3 grid(N / 64, M / 64, ks);
        fp16_gemm_kernel<64, 64><<<grid, 256, SMB>>>(Ah, Al, Bh, C, Chi, Clo,
                                                     M, N, K, flags);
    }
}

// ---------------- SIMT fp32 GEMM (embed only) ----------------
#define BMs 64
#define BNs 64
#define BKK 16
__global__ void gemm_kernel(const float* __restrict__ A, const float* __restrict__ B,
                            const float* __restrict__ bias, float* __restrict__ C,
                            int M, int N, int K, int lda, int ldb, int ldc) {
    __shared__ float As[BKK][BMs + 4];
    __shared__ float Bs[BKK][BNs + 4];
    int tid = threadIdx.y * 16 + threadIdx.x;
    int rowBase = blockIdx.y * BMs;
    int colBase = blockIdx.x * BNs;
    int r0 = threadIdx.y * 4, c0 = threadIdx.x * 4;
    float acc[4][4] = {};
    int aRow = tid >> 2;
    int aK   = (tid & 3) * 4;
    int bRow = tid >> 4;
    int bCol = (tid & 15) * 4;

    for (int kk = 0; kk < K; kk += BKK) {
        {
            int gr = rowBase + aRow;
            float4 v = make_float4(0.f, 0.f, 0.f, 0.f);
            if (gr < M) v = *(const float4*)(A + (size_t)gr * lda + kk + aK);
            As[aK + 0][aRow] = v.x; As[aK + 1][aRow] = v.y;
            As[aK + 2][aRow] = v.z; As[aK + 3][aRow] = v.w;
        }
        {
            int gc = colBase + bCol;
            float4 v = make_float4(0.f, 0.f, 0.f, 0.f);
            if (gc < N) v = *(const float4*)(B + (size_t)(kk + bRow) * ldb + gc);
            Bs[bRow][bCol + 0] = v.x; Bs[bRow][bCol + 1] = v.y;
            Bs[bRow][bCol + 2] = v.z; Bs[bRow][bCol + 3] = v.w;
        }
        __syncthreads();
#pragma unroll
        for (int k = 0; k < BKK; k++) {
            float a[4], bb[4];
#pragma unroll
            for (int i = 0; i < 4; i++) a[i] = As[k][r0 + i];
#pragma unroll
            for (int j = 0; j < 4; j++) bb[j] = Bs[k][c0 + j];
#pragma unroll
            for (int i = 0; i < 4; i++)
#pragma unroll
                for (int j = 0; j < 4; j++) acc[i][j] += a[i] * bb[j];
        }
        __syncthreads();
    }
#pragma unroll
    for (int i = 0; i < 4; i++) {
        int r = rowBase + r0 + i;
        if (r >= M) continue;
#pragma unroll
        for (int j = 0; j < 4; j++) {
            int c = colBase + c0 + j;
            if (c >= N) continue;
            C[(size_t)r * ldc + c] = acc[i][j] + bias[c];
        }
    }
}

// ---------------- attention with fused KV-cache append ----------------
__global__ void attn_kernel(const float* __restrict__ qkv, float* __restrict__ Kc,
                            float* __restrict__ Vc,
                            __half* __restrict__ outh, __half* __restrict__ outl,
                            int N, int C, int off) {
    int bh = blockIdx.x; int b = bh / NH, h = bh % NH;
    int n = threadIdx.y, lane = threadIdx.x;
    int t = b * N + n;
    size_t src = (size_t)t * 3 * DMODEL + h * HDIM;
    size_t dst = ((size_t)b * CMAX + off + n) * DMODEL + h * HDIM;
    Kc[dst + lane]      = qkv[src + DMODEL + lane];
    Kc[dst + lane + 32] = qkv[src + DMODEL + lane + 32];
    Vc[dst + lane]      = qkv[src + 2 * DMODEL + lane];
    Vc[dst + lane + 32] = qkv[src + 2 * DMODEL + lane + 32];
    __syncthreads();

    const float* q = qkv + src;
    int lim = n + off;
    float s = -1e30f;
    if (lane < C && lane <= lim) {
        const float* kr = Kc + ((size_t)b * CMAX + lane) * DMODEL + h * HDIM;
        float d = 0.f;
#pragma unroll
        for (int i = 0; i < HDIM; i++) d += q[i] * kr[i];
        s = d * 0.125f;
    }
    float mx = s;
#pragma unroll
    for (int o = 16; o; o >>= 1) mx = fmaxf(mx, __shfl_xor_sync(0xffffffffu, mx, o));
    float p = (lane < C && lane <= lim) ? expf(s - mx) : 0.f;
    float sum = warpSum(p);
    float a0 = 0.f, a1 = 0.f;
    int mmax = min(lim, C - 1);
    for (int m = 0; m <= mmax; m++) {
        float pm = __shfl_sync(0xffffffffu, p, m);
        const float* vr = Vc + ((size_t)b * CMAX + m) * DMODEL + h * HDIM;
        a0 += pm * vr[lane];
        a1 += pm * vr[lane + 32];
    }
    float inv = 1.f / sum;
    float v0 = a0 * inv, v1 = a1 * inv;
    size_t i0 = (size_t)t * DMODEL + h * HDIM + lane;
    __half h0, l0, h1, l1;
    split_fp16(v0, h0, l0); split_fp16(v1, h1, l1);
    outh[i0] = h0;      outl[i0] = l0;
    outh[i0 + 32] = h1; outl[i0 + 32] = l1;
}

// ---------------- output assembly ----------------
__global__ void assemble_kernel(float* __restrict__ out) {
    int idx = blockIdx.x * blockDim.x + threadIdx.x;
    int b = idx / 256, t = idx % 256;
    float m;
    if (t < 128) {
        m = 0.5f * (g_last[b * 128 + t] - g_last[(b + 32) * 128 + t]);
    } else {
        int o = t - 128;
        float va = g_no2[b * 128 + o]        * (g_nsg[b * 4 + 3] + EPSF)        + g_nmu[b * 4 + 3];
        float vb = g_no2[(b + 32) * 128 + o] * (g_nsg[(b + 32) * 4 + 3] + EPSF) + g_nmu[(b + 32) * 4 + 3];
        m = 0.5f * (va - vb);
    }
    if (g_ispos[b]) m = fmaxf(m, 0.f);
    out[idx] = m;
}

// ---------------- pointers bundle ----------------
struct DevPtrs {
    float *normed, *anorm, *hdd, *xn, *qkv, *Kc, *Vc, *no1, *no2;
    __half *xnh, *xnl, *atth, *attl, *h1h, *h1l;
    __half *qkvh, *woh, *w1h, *w2h;
};

// ---------------- full transformer forward ----------------
static void model_fwd_host(const DevPtrs& P, int T, int N, int C, int off,
                           const float* in_tok,
                           const float* W_in, const float* b_in, const float* ln1,
                           const float* ln2, const float* lnf,
                           float* nosel, int selStart, int selStep) {
    dim3 eg((DMODEL + BNs - 1) / BNs, (T + BMs - 1) / BMs), eb(16, 16);
    gemm_kernel<<<eg, eb>>>(in_tok, W_in, b_in, P.hdd, T, DMODEL, PATCH,
                            PATCH, DMODEL, DMODEL);
    for (int l = 0; l < NLAYER; l++) {
        ln_fp16_kernel<<<T, 256>>>(P.hdd, ln1 + (size_t)l * DMODEL, P.xnh, P.xnl);
        launch_fp16(P.xnh, P.xnl, P.qkvh + (size_t)l * 3072 * 1024,
                    P.qkv, nullptr, nullptr, T, 3 * DMODEL, DMODEL, 0);
        float* Kl = P.Kc + (size_t)l * NB * CMAX * DMODEL;
        float* Vl = P.Vc + (size_t)l * NB * CMAX * DMODEL;
        attn_kernel<<<NB * NH, dim3(32, N)>>>(P.qkv, Kl, Vl, P.atth, P.attl, N, C, off);
        launch_fp16(P.atth, P.attl, P.woh + (size_t)l * 1024 * 1024,
                    P.hdd, nullptr, nullptr, T, DMODEL, DMODEL, 1);
        ln_fp16_kernel<<<T, 256>>>(P.hdd, ln2 + (size_t)l * DMODEL, P.xnh, P.xnl);
        launch_fp16(P.xnh, P.xnl, P.w1h + (size_t)l * 4096 * 1024,
                    nullptr, P.h1h, P.h1l, T, NDFF, DMODEL, 2);
        launch_fp16(P.h1h, P.h1l, P.w2h + (size_t)l * 1024 * 4096,
                    P.hdd, nullptr, nullptr, T, DMODEL, NDFF, 1);
    }
    ln_kernel<<<T, 256>>>(P.hdd, lnf, P.xn);
    wout_kernel<<<8, 128>>>(P.xn, nosel, selStart, selStep);
}

// ---------------- entry ----------------
extern "C" void kernel_launch(void* const* d_in, const int* in_sizes, int n_in,
                              void* d_out, int out_size) {
    const float* x     = (const float*)d_in[0];
    const float* W_in  = (const float*)d_in[1];
    const float* b_in  = (const float*)d_in[2];
    const float* ln1_s = (const float*)d_in[3];
    const float* Wqkv  = (const float*)d_in[4];
    const float* Wo    = (const float*)d_in[5];
    const float* ln2_s = (const float*)d_in[6];
    const float* W1    = (const float*)d_in[7];
    const float* W2    = (const float*)d_in[8];
    const float* lnf_s = (const float*)d_in[9];
    const float* Wout  = (const float*)d_in[10];
    // d_in[11] = Wqs: provably unused for the median (channel-5) output

    DevPtrs P;
    cudaGetSymbolAddress((void**)&P.normed, g_normed);
    cudaGetSymbolAddress((void**)&P.anorm,  g_anorm);
    cudaGetSymbolAddress((void**)&P.hdd,    g_hdd);
    cudaGetSymbolAddress((void**)&P.xn,     g_xn);
    cudaGetSymbolAddress((void**)&P.qkv,    g_qkv);
    cudaGetSymbolAddress((void**)&P.Kc,     g_Kc);
    cudaGetSymbolAddress((void**)&P.Vc,     g_Vc);
    cudaGetSymbolAddress((void**)&P.no1,    g_no1);
    cudaGetSymbolAddress((void**)&P.no2,    g_no2);
    cudaGetSymbolAddress((void**)&P.xnh,    g_xnh);
    cudaGetSymbolAddress((void**)&P.xnl,    g_xnl);
    cudaGetSymbolAddress((void**)&P.atth,   g_atth);
    cudaGetSymbolAddress((void**)&P.attl,   g_attl);
    cudaGetSymbolAddress((void**)&P.h1h,    g_h1h);
    cudaGetSymbolAddress((void**)&P.h1l,    g_h1l);
    cudaGetSymbolAddress((void**)&P.qkvh,   g_Wqkvh);
    cudaGetSymbolAddress((void**)&P.woh,    g_Woh);
    cudaGetSymbolAddress((void**)&P.w1h,    g_W1h);
    cudaGetSymbolAddress((void**)&P.w2h,    g_W2h);

    // Stage 0: weight transpose + fp16 convert (hi only) + Wout columns
    convT_kernel<<<dim3(3072 / 32, 1024 / 32, NLAYER), dim3(32, 8)>>>(Wqkv, P.qkvh, 1024, 3072);
    convT_kernel<<<dim3(1024 / 32, 1024 / 32, NLAYER), dim3(32, 8)>>>(Wo,   P.woh,  1024, 1024);
    convT_kernel<<<dim3(4096 / 32, 1024 / 32, NLAYER), dim3(32, 8)>>>(W1,   P.w1h,  1024, 4096);
    convT_kernel<<<dim3(1024 / 32, 4096 / 32, NLAYER), dim3(32, 8)>>>(W2,   P.w2h,  4096, 1024);
    wsel_kernel<<<512, 256>>>(Wout);

    // Stage A: running stats + normalization for x and -x (batch 64)
    stats_kernel<<<NB, 32>>>(x);

    // Stage B: prefill (C=16, offset 0)
    model_fwd_host(P, T1, NPATCH, 16, 0, P.normed,
                   W_in, b_in, ln1_s, ln2_s, lnf_s,
                   P.no1, /*selStart=*/15, /*selStep=*/16);

    // Stage C: fused revin + AR stats, then one autoregressive step
    revin_ar_stats_kernel<<<NB, 32>>>();
    model_fwd_host(P, T2, 4, 20, 16, P.anorm,
                   W_in, b_in, ln1_s, ln2_s, lnf_s,
                   P.no2, /*selStart=*/3, /*selStep=*/4);

    // Stage D: combine x / -x, clamp, write [32,256]
    assemble_kernel<<<32, 256>>>((float*)d_out);
}

// round 16
// speedup vs baseline: 1.0724x; 1.0724x over previous
#include <cuda_runtime.h>
#include <cuda_fp16.h>
#include <math.h>
#include <stdint.h>

// Legacy mma.sync path (tcgen05 blocked by sm_103 ptxas target); HMMA fp32-acc
// pipe measured 100% saturated at ~272 TF/s -> only MMA count matters.
// R16: attention-path GEMMs (QKV, Wo) drop the A-correction term (1 MMA/k16);
// FFN GEMMs (W1, W2) keep 2-term. Predicted rel_err ~7.6e-4 (measured B-only
// quantization = 6.58e-4; attention A-quant adds sqrt(1/3) of that in RSS).

// ---------------- constants ----------------
#define NB      64
#define NPATCH  16
#define PATCH   32
#define DMODEL  1024
#define NH      16
#define HDIM    64
#define NDFF    4096
#define NLAYER  8
#define CMAX    20
#define T1      1024
#define T2      256
#define EPSF    1e-6f

// ---------------- device scratch ----------------
__device__ float g_normed[T1 * PATCH];
__device__ float g_anorm [T2 * PATCH];
__device__ float g_ctxmu [NB * NPATCH];
__device__ float g_ctxsg [NB * NPATCH];
__device__ float g_nmu   [NB * 4];
__device__ float g_nsg   [NB * 4];
__device__ int   g_ispos [32];
__device__ float g_hdd [T1 * DMODEL];
__device__ float g_xn  [T1 * DMODEL];
__device__ float g_qkv [T1 * 3 * DMODEL];
__device__ float g_Kc  [NLAYER * NB * CMAX * DMODEL];
__device__ float g_Vc  [NLAYER * NB * CMAX * DMODEL];
__device__ float g_no1 [NB * 128];
__device__ float g_no2 [NB * 128];
__device__ float g_last[NB * 128];
__device__ float g_Wsel[1024 * 128];

// fp16 hi/lo activation buffers (A side of GEMMs)
__device__ __half g_xnh [T1 * DMODEL], g_xnl [T1 * DMODEL];
__device__ __half g_atth[T1 * DMODEL];
__device__ __half g_h1h [T1 * NDFF],   g_h1l [T1 * NDFF];

// transposed fp16 weights (hi only): [L][N][K]
__device__ __half g_Wqkvh[(size_t)NLAYER * 3072 * 1024];
__device__ __half g_Woh [(size_t)NLAYER * 1024 * 1024];
__device__ __half g_W1h [(size_t)NLAYER * 4096 * 1024];
__device__ __half g_W2h [(size_t)NLAYER * 1024 * 4096];

// ---------------- helpers ----------------
__device__ __forceinline__ float warpSum(float v) {
#pragma unroll
    for (int o = 16; o; o >>= 1) v += __shfl_xor_sync(0xffffffffu, v, o);
    return v;
}

__device__ __forceinline__ float gelu_tanh(float x) {
    float x3 = x * x * x;
    return 0.5f * x * (1.0f + tanhf(0.7978845608028654f * (x + 0.044715f * x3)));
}

__device__ __forceinline__ void split_fp16(float v, __half& h, __half& l) {
    h = __float2half_rn(v);
    l = __float2half_rn(v - __half2float(h));
}

// ---------------- weight transpose + fp16 convert (hi only) ----------------
__global__ void convT_kernel(const float* __restrict__ W,
                             __half* __restrict__ Th, int K, int N) {
    __shared__ float t[32][33];
    int l = blockIdx.z;
    const float* Wl = W + (size_t)l * K * N;
    __half* Thl = Th + (size_t)l * K * N;
    int n0 = blockIdx.x * 32, k0 = blockIdx.y * 32;
#pragma unroll
    for (int i = 0; i < 4; i++)
        t[threadIdx.y + 8 * i][threadIdx.x] =
            Wl[(size_t)(k0 + threadIdx.y + 8 * i) * N + n0 + threadIdx.x];
    __syncthreads();
#pragma unroll
    for (int i = 0; i < 4; i++) {
        int n = threadIdx.y + 8 * i;
        Thl[(size_t)(n0 + n) * K + k0 + threadIdx.x] = __float2half_rn(t[threadIdx.x][n]);
    }
}

// ---------------- Wout channel-5 column extraction ----------------
__global__ void wsel_kernel(const float* __restrict__ Wout) {
    int i = blockIdx.x * blockDim.x + threadIdx.x;
    int k = i >> 7, j = i & 127;
    g_Wsel[i] = Wout[k * 1280 + 5 + 10 * j];
}

__global__ void wout_kernel(const float* __restrict__ xn, float* __restrict__ outv,
                            int selStart, int selStep) {
    __shared__ float sx[8][1024];
    int j = threadIdx.x;
    int b0 = blockIdx.x * 8;
#pragma unroll
    for (int i = 0; i < 8; i++) {
        int row = selStart + (b0 + i) * selStep;
        for (int c = j; c < 1024; c += 128) sx[i][c] = xn[(size_t)row * 1024 + c];
    }
    __syncthreads();
    float acc[8] = {};
    for (int k = 0; k < 1024; k++) {
        float w = g_Wsel[k * 128 + j];
#pragma unroll
        for (int i = 0; i < 8; i++) acc[i] += sx[i][k] * w;
    }
#pragma unroll
    for (int i = 0; i < 8; i++) outv[(b0 + i) * 128 + j] = acc[i];
}

// ---------------- running stats ----------------
__global__ void stats_kernel(const float* __restrict__ x) {
    int b = blockIdx.x, lane = threadIdx.x;
    const float* xb = x + (size_t)(b & 31) * 512;
    float sign = (b < 32) ? 1.f : -1.f;
    if (b < 32) {
        bool ok = true;
        for (int i = lane; i < 512; i += 32) ok = ok && (xb[i] >= 0.f);
        unsigned bal = __ballot_sync(0xffffffffu, ok);
        if (lane == 0) g_ispos[b] = (bal == 0xffffffffu) ? 1 : 0;
    }
    float n = 0.f, mu = 0.f, sg = 0.f;
    for (int p = 0; p < NPATCH; p++) {
        float v = sign * xb[p * PATCH + lane];
        float s = warpSum(v);
        float nn = n + 32.f;
        float nmu = (n * mu + s) / nn;
        float m2 = n * sg * sg + warpSum((v - mu) * (v - nmu));
        float nsg = sqrtf(fmaxf(m2 / nn, 1e-12f));
        n = nn; mu = nmu; sg = nsg;
        if (lane == 0) { g_ctxmu[b * NPATCH + p] = mu; g_ctxsg[b * NPATCH + p] = sg; }
        g_normed[(b * NPATCH + p) * PATCH + lane] = (v - mu) / (sg + EPSF);
    }
}

// fused: revin(last prefill output) -> g_last, then AR Welford stats -> g_anorm
__global__ void revin_ar_stats_kernel() {
    int b = blockIdx.x, lane = threadIdx.x;
    float mu0 = g_ctxmu[b * NPATCH + 15], sg0 = g_ctxsg[b * NPATCH + 15];
    float scale = sg0 + EPSF;
    float n = 512.f, mu = mu0, sg = sg0;
    for (int p = 0; p < 4; p++) {
        float v = g_no1[b * 128 + p * 32 + lane] * scale + mu0;
        g_last[b * 128 + p * 32 + lane] = v;
        float s = warpSum(v);
        float nn = n + 32.f;
        float nmu = (n * mu + s) / nn;
        float m2 = n * sg * sg + warpSum((v - mu) * (v - nmu));
        float ns = sqrtf(fmaxf(m2 / nn, 1e-12f));
        n = nn; mu = nmu; sg = ns;
        if (lane == 0) { g_nmu[b * 4 + p] = mu; g_nsg[b * 4 + p] = ns; }
        g_anorm[(b * 4 + p) * 32 + lane] = (v - mu) / (sg + EPSF);
    }
}

// ---------------- layernorms (single-pass: E[x], E[x^2]) ----------------
__global__ void ln_kernel(const float* __restrict__ in, const float* __restrict__ sc,
                          float* __restrict__ out) {
    __shared__ float row[DMODEL];
    __shared__ float red1[8], red2[8];
    __shared__ float s_mean, s_inv;
    int r = blockIdx.x, tid = threadIdx.x;
    const float* xr = in + (size_t)r * DMODEL;
    float s1 = 0.f, s2 = 0.f;
    for (int c = tid; c < DMODEL; c += 256) {
        float v = xr[c]; row[c] = v; s1 += v; s2 += v * v;
    }
    s1 = warpSum(s1); s2 = warpSum(s2);
    if ((tid & 31) == 0) { red1[tid >> 5] = s1; red2[tid >> 5] = s2; }
    __syncthreads();
    if (tid < 8) {
        float t1 = red1[tid], t2 = red2[tid];
#pragma unroll
        for (int o = 4; o; o >>= 1) {
            t1 += __shfl_xor_sync(0xffu, t1, o);
            t2 += __shfl_xor_sync(0xffu, t2, o);
        }
        if (tid == 0) {
            float m = t1 / (float)DMODEL;
            s_mean = m;
            s_inv = rsqrtf(fmaxf(t2 / (float)DMODEL - m * m, 0.f) + EPSF);
        }
    }
    __syncthreads();
    float m = s_mean, inv = s_inv;
    for (int c = tid; c < DMODEL; c += 256)
        out[(size_t)r * DMODEL + c] = (row[c] - m) * inv * sc[c];
}

__global__ void ln_fp16_kernel(const float* __restrict__ in, const float* __restrict__ sc,
                               __half* __restrict__ oh, __half* __restrict__ ol) {
    __shared__ float row[DMODEL];
    __shared__ float red1[8], red2[8];
    __shared__ float s_mean, s_inv;
    int r = blockIdx.x, tid = threadIdx.x;
    const float* xr = in + (size_t)r * DMODEL;
    float s1 = 0.f, s2 = 0.f;
    for (int c = tid; c < DMODEL; c += 256) {
        float v = xr[c]; row[c] = v; s1 += v; s2 += v * v;
    }
    s1 = warpSum(s1); s2 = warpSum(s2);
    if ((tid & 31) == 0) { red1[tid >> 5] = s1; red2[tid >> 5] = s2; }
    __syncthreads();
    if (tid < 8) {
        float t1 = red1[tid], t2 = red2[tid];
#pragma unroll
        for (int o = 4; o; o >>= 1) {
            t1 += __shfl_xor_sync(0xffu, t1, o);
            t2 += __shfl_xor_sync(0xffu, t2, o);
        }
        if (tid == 0) {
            float m = t1 / (float)DMODEL;
            s_mean = m;
            s_inv = rsqrtf(fmaxf(t2 / (float)DMODEL - m * m, 0.f) + EPSF);
        }
    }
    __syncthreads();
    float m = s_mean, inv = s_inv;
    for (int c = tid; c < DMODEL; c += 256) {
        float v = (row[c] - m) * inv * sc[c];
        __half h, lo; split_fp16(v, h, lo);
        oh[(size_t)r * DMODEL + c] = h;
        ol[(size_t)r * DMODEL + c] = lo;
    }
}

// ================= fp16 GEMM: TERMS=2 (Ah+Al)·Bh or TERMS=1 Ah·Bh ===========
#define MMA_F16F32(d, a, b)                                                     \
    asm volatile(                                                               \
        "mma.sync.aligned.m16n8k16.row.col.f32.f16.f16.f32 "                    \
        "{%0,%1,%2,%3},{%4,%5,%6,%7},{%8,%9},{%0,%1,%2,%3};"                    \
        : "+f"((d)[0]), "+f"((d)[1]), "+f"((d)[2]), "+f"((d)[3])                \
        : "r"((a)[0]), "r"((a)[1]), "r"((a)[2]), "r"((a)[3]),                   \
          "r"((b)[0]), "r"((b)[1]))

#define LDSM4(r0, r1, r2, r3, addr)                                             \
    asm volatile("ldmatrix.sync.aligned.m8n8.x4.shared.b16 {%0,%1,%2,%3},[%4];" \
        : "=r"(r0), "=r"(r1), "=r"(r2), "=r"(r3) : "r"(addr))

#define CP16(dst, src)                                                          \
    asm volatile("cp.async.cg.shared.global [%0], [%1], 16;" ::                 \
                 "r"(dst), "l"(src) : "memory")

#define CPCOMMIT() asm volatile("cp.async.commit_group;" ::: "memory")

// stage layout: [Ah: BM rows][Al: BM rows, TERMS==2 only][Bh: BN rows], 128B rows
template<int BM, int BN, int TERMS>
__device__ __forceinline__ void load_stage_fn(uint32_t base, int tid,
        const __half* __restrict__ Ah, const __half* __restrict__ Al,
        const __half* __restrict__ Bh, int K, int kt) {
#pragma unroll
    for (int i = 0; i < BM * 8 / 256; i++) {
        int cid = tid + i * 256;
        int r = cid >> 3, c = cid & 7;
        CP16(base + r * 128 + ((c ^ (r & 7)) << 4),
             Ah + (size_t)r * K + kt * 64 + c * 8);
    }
    if (TERMS == 2) {
#pragma unroll
        for (int i = 0; i < BM * 8 / 256; i++) {
            int cid = tid + i * 256;
            int r = cid >> 3, c = cid & 7;
            CP16(base + BM * 128 + r * 128 + ((c ^ (r & 7)) << 4),
                 Al + (size_t)r * K + kt * 64 + c * 8);
        }
    }
#pragma unroll
    for (int i = 0; i < BN * 8 / 256; i++) {
        int cid = tid + i * 256;
        int r = cid >> 3, c = cid & 7;
        CP16(base + TERMS * BM * 128 + r * 128 + ((c ^ (r & 7)) << 4),
             Bh + (size_t)r * K + kt * 64 + c * 8);
    }
}

template<int BM, int BN, int TERMS>
__global__ void __launch_bounds__(256, (TERMS == 2 && BN == 128) ? 2 : 3)
fp16_gemm_kernel(
        const __half* __restrict__ Ah, const __half* __restrict__ Al,
        const __half* __restrict__ Bh,
        float* __restrict__ C, __half* __restrict__ Chi, __half* __restrict__ Clo,
        int M, int N, int K, int flags) {
    extern __shared__ __align__(128) char smem[];
    constexpr int ASTAGE = BM * 128;
    constexpr int STAGE  = (TERMS * BM + BN) * 128;
    uint32_t smBase = (uint32_t)__cvta_generic_to_shared(smem);

    const int tid  = threadIdx.x;
    const int lane = tid & 31;
    const int gid  = lane >> 2;
    const int tig  = lane & 3;
    const int warp = tid >> 5;
    constexpr int MT = (BM / 2) / 16;
    constexpr int NT = (BN / 4) / 8;
    const int wm = warp & 1, wn = warp >> 1;
    const int mBase = wm * (BM / 2);
    const int nBase = wn * (BN / 4);
    const int blockRow = blockIdx.y * BM;
    const int blockCol = blockIdx.x * BN;

    const __half* Ah0 = Ah + (size_t)blockRow * K;
    const __half* Al0 = Al + (size_t)blockRow * K;
    const __half* Bh0 = Bh + (size_t)blockCol * K;

    float acc[MT][NT][4];
#pragma unroll
    for (int i = 0; i < MT; i++)
#pragma unroll
        for (int j = 0; j < NT; j++)
#pragma unroll
            for (int q = 0; q < 4; q++) acc[i][j][q] = 0.f;

    const int ktiles = K / 64;
    const int ksl = ktiles / gridDim.z;
    const int kt0 = ksl * blockIdx.z;

    const int arow = (lane & 7) + ((lane >> 3) & 1) * 8;
    const int acsel = lane >> 4;
    const int nrow = lane & 7;
    const int bcsel = (lane >> 3) & 1;
    const int ntsel = lane >> 4;

    load_stage_fn<BM, BN, TERMS>(smBase, tid, Ah0, Al0, Bh0, K, kt0);
    CPCOMMIT();
    load_stage_fn<BM, BN, TERMS>(smBase + STAGE, tid, Ah0, Al0, Bh0, K, kt0 + 1);
    CPCOMMIT();

    for (int ktl = 0; ktl < ksl; ktl++) {
        asm volatile("cp.async.wait_group 1;" ::: "memory");
        __syncthreads();
        if (ktl + 2 < ksl)
            load_stage_fn<BM, BN, TERMS>(smBase + ((ktl + 2) % 3) * STAGE, tid,
                                         Ah0, Al0, Bh0, K, kt0 + ktl + 2);
        CPCOMMIT();

        uint32_t AhA = smBase + (ktl % 3) * STAGE;
        uint32_t AlA = AhA + ASTAGE;
        uint32_t BhA = AhA + TERMS * ASTAGE;
#pragma unroll
        for (int s = 0; s < 4; s++) {
            const int ck = 2 * s;
            uint32_t bh[NT][2];
#pragma unroll
            for (int np = 0; np < NT / 2; np++) {
                int nt0 = np * 2;
                int r = nBase + (nt0 + ntsel) * 8 + nrow;
                LDSM4(bh[nt0][0], bh[nt0][1], bh[nt0 + 1][0], bh[nt0 + 1][1],
                      BhA + r * 128 + (((ck + bcsel) ^ (r & 7)) << 4));
            }
#pragma unroll
            for (int mt = 0; mt < MT; mt++) {
                int r = mBase + mt * 16 + arow;
                int xo = ((ck + acsel) ^ (r & 7)) << 4;
                uint32_t ah[4];
                LDSM4(ah[0], ah[1], ah[2], ah[3], AhA + r * 128 + xo);
#pragma unroll
                for (int nt = 0; nt < NT; nt++) MMA_F16F32(acc[mt][nt], ah, bh[nt]);
                if (TERMS == 2) {
                    uint32_t al[4];
                    LDSM4(al[0], al[1], al[2], al[3], AlA + r * 128 + xo);
#pragma unroll
                    for (int nt = 0; nt < NT; nt++) MMA_F16F32(acc[mt][nt], al, bh[nt]);
                }
            }
        }
    }

    // epilogue
    const bool multiZ = (gridDim.z > 1);
#pragma unroll
    for (int mt = 0; mt < MT; mt++) {
#pragma unroll
        for (int nt = 0; nt < NT; nt++) {
            int col = blockCol + nBase + nt * 8 + tig * 2;
            float* a = acc[mt][nt];
#pragma unroll
            for (int hh = 0; hh < 2; hh++) {
                int row = blockRow + mBase + mt * 16 + gid + hh * 8;
                size_t o = (size_t)row * N + col;
                float v0 = a[hh * 2 + 0], v1 = a[hh * 2 + 1];
                if (flags == 2) {
                    float g0 = gelu_tanh(v0), g1 = gelu_tanh(v1);
                    __half h0, l0, h1, l1;
                    split_fp16(g0, h0, l0); split_fp16(g1, h1, l1);
                    Chi[o] = h0; Clo[o] = l0; Chi[o + 1] = h1; Clo[o + 1] = l1;
                } else if (flags == 1) {
                    if (multiZ) { atomicAdd(&C[o], v0); atomicAdd(&C[o + 1], v1); }
                    else        { C[o] += v0; C[o + 1] += v1; }
                } else {
                    C[o] = v0; C[o + 1] = v1;
                }
            }
        }
    }
}

static void launch_fp16(const __half* Ah, const __half* Al, const __half* Bh,
                        float* C, __half* Chi, __half* Clo,
                        int M, int N, int K, int flags, int terms) {
    if (M >= 1024 && N >= 2048) {            // QKV (terms=1) / W1 (terms=2) prefill
        if (terms == 1) {
            constexpr int SMB = 3 * (64 + 128) * 128;
            cudaFuncSetAttribute(fp16_gemm_kernel<64, 128, 1>,
                                 cudaFuncAttributeMaxDynamicSharedMemorySize, SMB);
            dim3 grid(N / 128, M / 64);
            fp16_gemm_kernel<64, 128, 1><<<grid, 256, SMB>>>(Ah, Al, Bh, C, Chi, Clo,
                                                             M, N, K, flags);
        } else {
            constexpr int SMB = 3 * (2 * 64 + 128) * 128;
            cudaFuncSetAttribute(fp16_gemm_kernel<64, 128, 2>,
                                 cudaFuncAttributeMaxDynamicSharedMemorySize, SMB);
            dim3 grid(N / 128, M / 64);
            fp16_gemm_kernel<64, 128, 2><<<grid, 256, SMB>>>(Ah, Al, Bh, C, Chi, Clo,
                                                             M, N, K, flags);
        }
    } else {
        int ks = (flags == 1 && M < 1024 && N <= 1024) ? 4 : 1;
        dim3 grid(N / 64, M / 64, ks);
        if (terms == 1) {
            constexpr int SMB = 3 * (64 + 64) * 128;
            cudaFuncSetAttribute(fp16_gemm_kernel<64, 64, 1>,
                                 cudaFuncAttributeMaxDynamicSharedMemorySize, SMB);
            fp16_gemm_kernel<64, 64, 1><<<grid, 256, SMB>>>(Ah, Al, Bh, C, Chi, Clo,
                                                            M, N, K, flags);
        } else {
            constexpr int SMB = 3 * (2 * 64 + 64) * 128;
            cudaFuncSetAttribute(fp16_gemm_kernel<64, 64, 2>,
                                 cudaFuncAttributeMaxDynamicSharedMemorySize, SMB);
            fp16_gemm_kernel<64, 64, 2><<<grid, 256, SMB>>>(Ah, Al, Bh, C, Chi, Clo,
                                                            M, N, K, flags);
        }
    }
}

// ---------------- SIMT fp32 GEMM (embed only) ----------------
#define BMs 64
#define BNs 64
#define BKK 16
__global__ void gemm_kernel(const float* __restrict__ A, const float* __restrict__ B,
                            const float* __restrict__ bias, float* __restrict__ C,
                            int M, int N, int K, int lda, int ldb, int ldc) {
    __shared__ float As[BKK][BMs + 4];
    __shared__ float Bs[BKK][BNs + 4];
    int tid = threadIdx.y * 16 + threadIdx.x;
    int rowBase = blockIdx.y * BMs;
    int colBase = blockIdx.x * BNs;
    int r0 = threadIdx.y * 4, c0 = threadIdx.x * 4;
    float acc[4][4] = {};
    int aRow = tid >> 2;
    int aK   = (tid & 3) * 4;
    int bRow = tid >> 4;
    int bCol = (tid & 15) * 4;

    for (int kk = 0; kk < K; kk += BKK) {
        {
            int gr = rowBase + aRow;
            float4 v = make_float4(0.f, 0.f, 0.f, 0.f);
            if (gr < M) v = *(const float4*)(A + (size_t)gr * lda + kk + aK);
            As[aK + 0][aRow] = v.x; As[aK + 1][aRow] = v.y;
            As[aK + 2][aRow] = v.z; As[aK + 3][aRow] = v.w;
        }
        {
            int gc = colBase + bCol;
            float4 v = make_float4(0.f, 0.f, 0.f, 0.f);
            if (gc < N) v = *(const float4*)(B + (size_t)(kk + bRow) * ldb + gc);
            Bs[bRow][bCol + 0] = v.x; Bs[bRow][bCol + 1] = v.y;
            Bs[bRow][bCol + 2] = v.z; Bs[bRow][bCol + 3] = v.w;
        }
        __syncthreads();
#pragma unroll
        for (int k = 0; k < BKK; k++) {
            float a[4], bb[4];
#pragma unroll
            for (int i = 0; i < 4; i++) a[i] = As[k][r0 + i];
#pragma unroll
            for (int j = 0; j < 4; j++) bb[j] = Bs[k][c0 + j];
#pragma unroll
            for (int i = 0; i < 4; i++)
#pragma unroll
                for (int j = 0; j < 4; j++) acc[i][j] += a[i] * bb[j];
        }
        __syncthreads();
    }
#pragma unroll
    for (int i = 0; i < 4; i++) {
        int r = rowBase + r0 + i;
        if (r >= M) continue;
#pragma unroll
        for (int j = 0; j < 4; j++) {
            int c = colBase + c0 + j;
            if (c >= N) continue;
            C[(size_t)r * ldc + c] = acc[i][j] + bias[c];
        }
    }
}

// ---------------- attention with fused KV-cache append (hi-only output) -----
__global__ void attn_kernel(const float* __restrict__ qkv, float* __restrict__ Kc,
                            float* __restrict__ Vc,
                            __half* __restrict__ outh,
                            int N, int C, int off) {
    int bh = blockIdx.x; int b = bh / NH, h = bh % NH;
    int n = threadIdx.y, lane = threadIdx.x;
    int t = b * N + n;
    size_t src = (size_t)t * 3 * DMODEL + h * HDIM;
    size_t dst = ((size_t)b * CMAX + off + n) * DMODEL + h * HDIM;
    Kc[dst + lane]      = qkv[src + DMODEL + lane];
    Kc[dst + lane + 32] = qkv[src + DMODEL + lane + 32];
    Vc[dst + lane]      = qkv[src + 2 * DMODEL + lane];
    Vc[dst + lane + 32] = qkv[src + 2 * DMODEL + lane + 32];
    __syncthreads();

    const float* q = qkv + src;
    int lim = n + off;
    float s = -1e30f;
    if (lane < C && lane <= lim) {
        const float* kr = Kc + ((size_t)b * CMAX + lane) * DMODEL + h * HDIM;
        float d = 0.f;
#pragma unroll
        for (int i = 0; i < HDIM; i++) d += q[i] * kr[i];
        s = d * 0.125f;
    }
    float mx = s;
#pragma unroll
    for (int o = 16; o; o >>= 1) mx = fmaxf(mx, __shfl_xor_sync(0xffffffffu, mx, o));
    float p = (lane < C && lane <= lim) ? expf(s - mx) : 0.f;
    float sum = warpSum(p);
    float a0 = 0.f, a1 = 0.f;
    int mmax = min(lim, C - 1);
    for (int m = 0; m <= mmax; m++) {
        float pm = __shfl_sync(0xffffffffu, p, m);
        const float* vr = Vc + ((size_t)b * CMAX + m) * DMODEL + h * HDIM;
        a0 += pm * vr[lane];
        a1 += pm * vr[lane + 32];
    }
    float inv = 1.f / sum;
    size_t i0 = (size_t)t * DMODEL + h * HDIM + lane;
    outh[i0]      = __float2half_rn(a0 * inv);
    outh[i0 + 32] = __float2half_rn(a1 * inv);
}

// ---------------- output assembly ----------------
__global__ void assemble_kernel(float* __restrict__ out) {
    int idx = blockIdx.x * blockDim.x + threadIdx.x;
    int b = idx / 256, t = idx % 256;
    float m;
    if (t < 128) {
        m = 0.5f * (g_last[b * 128 + t] - g_last[(b + 32) * 128 + t]);
    } else {
        int o = t - 128;
        float va = g_no2[b * 128 + o]        * (g_nsg[b * 4 + 3] + EPSF)        + g_nmu[b * 4 + 3];
        float vb = g_no2[(b + 32) * 128 + o] * (g_nsg[(b + 32) * 4 + 3] + EPSF) + g_nmu[(b + 32) * 4 + 3];
        m = 0.5f * (va - vb);
    }
    if (g_ispos[b]) m = fmaxf(m, 0.f);
    out[idx] = m;
}

// ---------------- pointers bundle ----------------
struct DevPtrs {
    float *normed, *anorm, *hdd, *xn, *qkv, *Kc, *Vc, *no1, *no2;
    __half *xnh, *xnl, *atth, *h1h, *h1l;
    __half *qkvh, *woh, *w1h, *w2h;
};

// ---------------- full transformer forward ----------------
static void model_fwd_host(const DevPtrs& P, int T, int N, int C, int off,
                           const float* in_tok,
                           const float* W_in, const float* b_in, const float* ln1,
                           const float* ln2, const float* lnf,
                           float* nosel, int selStart, int selStep) {
    dim3 eg((DMODEL + BNs - 1) / BNs, (T + BMs - 1) / BMs), eb(16, 16);
    gemm_kernel<<<eg, eb>>>(in_tok, W_in, b_in, P.hdd, T, DMODEL, PATCH,
                            PATCH, DMODEL, DMODEL);
    for (int l = 0; l < NLAYER; l++) {
        ln_fp16_kernel<<<T, 256>>>(P.hdd, ln1 + (size_t)l * DMODEL, P.xnh, P.xnl);
        launch_fp16(P.xnh, P.xnl, P.qkvh + (size_t)l * 3072 * 1024,
                    P.qkv, nullptr, nullptr, T, 3 * DMODEL, DMODEL, 0, /*terms=*/1);
        float* Kl = P.Kc + (size_t)l * NB * CMAX * DMODEL;
        float* Vl = P.Vc + (size_t)l * NB * CMAX * DMODEL;
        attn_kernel<<<NB * NH, dim3(32, N)>>>(P.qkv, Kl, Vl, P.atth, N, C, off);
        launch_fp16(P.atth, nullptr, P.woh + (size_t)l * 1024 * 1024,
                    P.hdd, nullptr, nullptr, T, DMODEL, DMODEL, 1, /*terms=*/1);
        ln_fp16_kernel<<<T, 256>>>(P.hdd, ln2 + (size_t)l * DMODEL, P.xnh, P.xnl);
        launch_fp16(P.xnh, P.xnl, P.w1h + (size_t)l * 4096 * 1024,
                    nullptr, P.h1h, P.h1l, T, NDFF, DMODEL, 2, /*terms=*/2);
        launch_fp16(P.h1h, P.h1l, P.w2h + (size_t)l * 1024 * 4096,
                    P.hdd, nullptr, nullptr, T, DMODEL, NDFF, 1, /*terms=*/2);
    }
    ln_kernel<<<T, 256>>>(P.hdd, lnf, P.xn);
    wout_kernel<<<8, 128>>>(P.xn, nosel, selStart, selStep);
}

// ---------------- entry ----------------
extern "C" void kernel_launch(void* const* d_in, const int* in_sizes, int n_in,
                              void* d_out, int out_size) {
    const float* x     = (const float*)d_in[0];
    const float* W_in  = (const float*)d_in[1];
    const float* b_in  = (const float*)d_in[2];
    const float* ln1_s = (const float*)d_in[3];
    const float* Wqkv  = (const float*)d_in[4];
    const float* Wo    = (const float*)d_in[5];
    const float* ln2_s = (const float*)d_in[6];
    const float* W1    = (const float*)d_in[7];
    const float* W2    = (const float*)d_in[8];
    const float* lnf_s = (const float*)d_in[9];
    const float* Wout  = (const float*)d_in[10];
    // d_in[11] = Wqs: provably unused for the median (channel-5) output

    DevPtrs P;
    cudaGetSymbolAddress((void**)&P.normed, g_normed);
    cudaGetSymbolAddress((void**)&P.anorm,  g_anorm);
    cudaGetSymbolAddress((void**)&P.hdd,    g_hdd);
    cudaGetSymbolAddress((void**)&P.xn,     g_xn);
    cudaGetSymbolAddress((void**)&P.qkv,    g_qkv);
    cudaGetSymbolAddress((void**)&P.Kc,     g_Kc);
    cudaGetSymbolAddress((void**)&P.Vc,     g_Vc);
    cudaGetSymbolAddress((void**)&P.no1,    g_no1);
    cudaGetSymbolAddress((void**)&P.no2,    g_no2);
    cudaGetSymbolAddress((void**)&P.xnh,    g_xnh);
    cudaGetSymbolAddress((void**)&P.xnl,    g_xnl);
    cudaGetSymbolAddress((void**)&P.atth,   g_atth);
    cudaGetSymbolAddress((void**)&P.h1h,    g_h1h);
    cudaGetSymbolAddress((void**)&P.h1l,    g_h1l);
    cudaGetSymbolAddress((void**)&P.qkvh,   g_Wqkvh);
    cudaGetSymbolAddress((void**)&P.woh,    g_Woh);
    cudaGetSymbolAddress((void**)&P.w1h,    g_W1h);
    cudaGetSymbolAddress((void**)&P.w2h,    g_W2h);

    // Stage 0: weight transpose + fp16 convert (hi only) + Wout columns
    convT_kernel<<<dim3(3072 / 32, 1024 / 32, NLAYER), dim3(32, 8)>>>(Wqkv, P.qkvh, 1024, 3072);
    convT_kernel<<<dim3(1024 / 32, 1024 / 32, NLAYER), dim3(32, 8)>>>(Wo,   P.woh,  1024, 1024);
    convT_kernel<<<dim3(4096 / 32, 1024 / 32, NLAYER), dim3(32, 8)>>>(W1,   P.w1h,  1024, 4096);
    convT_kernel<<<dim3(1024 / 32, 4096 / 32, NLAYER), dim3(32, 8)>>>(W2,   P.w2h,  4096, 1024);
    wsel_kernel<<<512, 256>>>(Wout);

    // Stage A: running stats + normalization for x and -x (batch 64)
    stats_kernel<<<NB, 32>>>(x);

    // Stage B: prefill (C=16, offset 0)
    model_fwd_host(P, T1, NPATCH, 16, 0, P.normed,
                   W_in, b_in, ln1_s, ln2_s, lnf_s,
                   P.no1, /*selStart=*/15, /*selStep=*/16);

    // Stage C: fused revin + AR stats, then one autoregressive step
    revin_ar_stats_kernel<<<NB, 32>>>();
    model_fwd_host(P, T2, 4, 20, 16, P.anorm,
                   W_in, b_in, ln1_s, ln2_s, lnf_s,
                   P.no2, /*selStart=*/3, /*selStep=*/4);

    // Stage D: combine x / -x, clamp, write [32,256]
    assemble_kernel<<<32, 256>>>((float*)d_out);
}

// round 17
// speedup vs baseline: 1.0964x; 1.0224x over previous
#include <cuda_runtime.h>
#include <cuda_fp16.h>
#include <math.h>
#include <stdint.h>

// Legacy mma.sync path (tcgen05 blocked by sm_103 ptxas target); HMMA fp32-acc
// pipe is the binding resource. R17: (1) widen accumulator-RAW distance in the
// GEMM inner loop (all A-LDSMs hoisted; hi MMAs over mt x nt, then lo MMAs ->
// same-acc reuse distance MT*NT instead of NT); (2) final LN fused into wout
// (only 64 of T rows are actually consumed).

// ---------------- constants ----------------
#define NB      64
#define NPATCH  16
#define PATCH   32
#define DMODEL  1024
#define NH      16
#define HDIM    64
#define NDFF    4096
#define NLAYER  8
#define CMAX    20
#define T1      1024
#define T2      256
#define EPSF    1e-6f

// ---------------- device scratch ----------------
__device__ float g_normed[T1 * PATCH];
__device__ float g_anorm [T2 * PATCH];
__device__ float g_ctxmu [NB * NPATCH];
__device__ float g_ctxsg [NB * NPATCH];
__device__ float g_nmu   [NB * 4];
__device__ float g_nsg   [NB * 4];
__device__ int   g_ispos [32];
__device__ float g_hdd [T1 * DMODEL];
__device__ float g_qkv [T1 * 3 * DMODEL];
__device__ float g_Kc  [NLAYER * NB * CMAX * DMODEL];
__device__ float g_Vc  [NLAYER * NB * CMAX * DMODEL];
__device__ float g_no1 [NB * 128];
__device__ float g_no2 [NB * 128];
__device__ float g_last[NB * 128];
__device__ float g_Wsel[1024 * 128];

// fp16 hi/lo activation buffers (A side of GEMMs)
__device__ __half g_xnh [T1 * DMODEL], g_xnl [T1 * DMODEL];
__device__ __half g_atth[T1 * DMODEL];
__device__ __half g_h1h [T1 * NDFF],   g_h1l [T1 * NDFF];

// transposed fp16 weights (hi only): [L][N][K]
__device__ __half g_Wqkvh[(size_t)NLAYER * 3072 * 1024];
__device__ __half g_Woh [(size_t)NLAYER * 1024 * 1024];
__device__ __half g_W1h [(size_t)NLAYER * 4096 * 1024];
__device__ __half g_W2h [(size_t)NLAYER * 1024 * 4096];

// ---------------- helpers ----------------
__device__ __forceinline__ float warpSum(float v) {
#pragma unroll
    for (int o = 16; o; o >>= 1) v += __shfl_xor_sync(0xffffffffu, v, o);
    return v;
}

__device__ __forceinline__ float gelu_tanh(float x) {
    float x3 = x * x * x;
    return 0.5f * x * (1.0f + tanhf(0.7978845608028654f * (x + 0.044715f * x3)));
}

__device__ __forceinline__ void split_fp16(float v, __half& h, __half& l) {
    h = __float2half_rn(v);
    l = __float2half_rn(v - __half2float(h));
}

// ---------------- weight transpose + fp16 convert (hi only) ----------------
__global__ void convT_kernel(const float* __restrict__ W,
                             __half* __restrict__ Th, int K, int N) {
    __shared__ float t[32][33];
    int l = blockIdx.z;
    const float* Wl = W + (size_t)l * K * N;
    __half* Thl = Th + (size_t)l * K * N;
    int n0 = blockIdx.x * 32, k0 = blockIdx.y * 32;
#pragma unroll
    for (int i = 0; i < 4; i++)
        t[threadIdx.y + 8 * i][threadIdx.x] =
            Wl[(size_t)(k0 + threadIdx.y + 8 * i) * N + n0 + threadIdx.x];
    __syncthreads();
#pragma unroll
    for (int i = 0; i < 4; i++) {
        int n = threadIdx.y + 8 * i;
        Thl[(size_t)(n0 + n) * K + k0 + threadIdx.x] = __float2half_rn(t[threadIdx.x][n]);
    }
}

// ---------------- Wout channel-5 column extraction ----------------
__global__ void wsel_kernel(const float* __restrict__ Wout) {
    int i = blockIdx.x * blockDim.x + threadIdx.x;
    int k = i >> 7, j = i & 127;
    g_Wsel[i] = Wout[k * 1280 + 5 + 10 * j];
}

// fused final-LN + Wout GEMM for the 64 selected rows only.
// grid 8 blocks x 256 threads; block handles 8 batch rows.
__global__ void wout_ln_kernel(const float* __restrict__ hdd,
                               const float* __restrict__ sc,
                               float* __restrict__ outv,
                               int selStart, int selStep) {
    __shared__ float sx[8][1024];
    int tid = threadIdx.x;
    int b0 = blockIdx.x * 8;
#pragma unroll
    for (int i = 0; i < 8; i++) {
        int row = selStart + (b0 + i) * selStep;
        for (int c = tid; c < 1024; c += 256)
            sx[i][c] = hdd[(size_t)row * 1024 + c];
    }
    __syncthreads();
    // LN: warp w owns row w
    int w = tid >> 5, lane = tid & 31;
    float s1 = 0.f, s2 = 0.f;
    for (int c = lane; c < 1024; c += 32) { float v = sx[w][c]; s1 += v; s2 += v * v; }
    s1 = warpSum(s1); s2 = warpSum(s2);
    float m = s1 / 1024.f;
    float inv = rsqrtf(fmaxf(s2 / 1024.f - m * m, 0.f) + EPSF);
    for (int c = lane; c < 1024; c += 32) sx[w][c] = (sx[w][c] - m) * inv * sc[c];
    __syncthreads();
    // dot: thread (g, j) handles rows g*4..g*4+3, column j
    int j = tid & 127, g = tid >> 7;
    float acc[4] = {};
    for (int k = 0; k < 1024; k++) {
        float wv = g_Wsel[k * 128 + j];
#pragma unroll
        for (int i = 0; i < 4; i++) acc[i] += sx[g * 4 + i][k] * wv;
    }
#pragma unroll
    for (int i = 0; i < 4; i++) outv[(b0 + g * 4 + i) * 128 + j] = acc[i];
}

// ---------------- running stats ----------------
__global__ void stats_kernel(const float* __restrict__ x) {
    int b = blockIdx.x, lane = threadIdx.x;
    const float* xb = x + (size_t)(b & 31) * 512;
    float sign = (b < 32) ? 1.f : -1.f;
    if (b < 32) {
        bool ok = true;
        for (int i = lane; i < 512; i += 32) ok = ok && (xb[i] >= 0.f);
        unsigned bal = __ballot_sync(0xffffffffu, ok);
        if (lane == 0) g_ispos[b] = (bal == 0xffffffffu) ? 1 : 0;
    }
    float n = 0.f, mu = 0.f, sg = 0.f;
    for (int p = 0; p < NPATCH; p++) {
        float v = sign * xb[p * PATCH + lane];
        float s = warpSum(v);
        float nn = n + 32.f;
        float nmu = (n * mu + s) / nn;
        float m2 = n * sg * sg + warpSum((v - mu) * (v - nmu));
        float nsg = sqrtf(fmaxf(m2 / nn, 1e-12f));
        n = nn; mu = nmu; sg = nsg;
        if (lane == 0) { g_ctxmu[b * NPATCH + p] = mu; g_ctxsg[b * NPATCH + p] = sg; }
        g_normed[(b * NPATCH + p) * PATCH + lane] = (v - mu) / (sg + EPSF);
    }
}

// fused: revin(last prefill output) -> g_last, then AR Welford stats -> g_anorm
__global__ void revin_ar_stats_kernel() {
    int b = blockIdx.x, lane = threadIdx.x;
    float mu0 = g_ctxmu[b * NPATCH + 15], sg0 = g_ctxsg[b * NPATCH + 15];
    float scale = sg0 + EPSF;
    float n = 512.f, mu = mu0, sg = sg0;
    for (int p = 0; p < 4; p++) {
        float v = g_no1[b * 128 + p * 32 + lane] * scale + mu0;
        g_last[b * 128 + p * 32 + lane] = v;
        float s = warpSum(v);
        float nn = n + 32.f;
        float nmu = (n * mu + s) / nn;
        float m2 = n * sg * sg + warpSum((v - mu) * (v - nmu));
        float ns = sqrtf(fmaxf(m2 / nn, 1e-12f));
        n = nn; mu = nmu; sg = ns;
        if (lane == 0) { g_nmu[b * 4 + p] = mu; g_nsg[b * 4 + p] = ns; }
        g_anorm[(b * 4 + p) * 32 + lane] = (v - mu) / (sg + EPSF);
    }
}

// ---------------- layernorm (single-pass, fp16 hi/lo out) ----------------
__global__ void ln_fp16_kernel(const float* __restrict__ in, const float* __restrict__ sc,
                               __half* __restrict__ oh, __half* __restrict__ ol) {
    __shared__ float row[DMODEL];
    __shared__ float red1[8], red2[8];
    __shared__ float s_mean, s_inv;
    int r = blockIdx.x, tid = threadIdx.x;
    const float* xr = in + (size_t)r * DMODEL;
    float s1 = 0.f, s2 = 0.f;
    for (int c = tid; c < DMODEL; c += 256) {
        float v = xr[c]; row[c] = v; s1 += v; s2 += v * v;
    }
    s1 = warpSum(s1); s2 = warpSum(s2);
    if ((tid & 31) == 0) { red1[tid >> 5] = s1; red2[tid >> 5] = s2; }
    __syncthreads();
    if (tid < 8) {
        float t1 = red1[tid], t2 = red2[tid];
#pragma unroll
        for (int o = 4; o; o >>= 1) {
            t1 += __shfl_xor_sync(0xffu, t1, o);
            t2 += __shfl_xor_sync(0xffu, t2, o);
        }
        if (tid == 0) {
            float m = t1 / (float)DMODEL;
            s_mean = m;
            s_inv = rsqrtf(fmaxf(t2 / (float)DMODEL - m * m, 0.f) + EPSF);
        }
    }
    __syncthreads();
    float m = s_mean, inv = s_inv;
    for (int c = tid; c < DMODEL; c += 256) {
        float v = (row[c] - m) * inv * sc[c];
        __half h, lo; split_fp16(v, h, lo);
        oh[(size_t)r * DMODEL + c] = h;
        ol[(size_t)r * DMODEL + c] = lo;
    }
}

// ================= fp16 GEMM: TERMS=2 (Ah+Al)·Bh or TERMS=1 Ah·Bh ===========
#define MMA_F16F32(d, a, b)                                                     \
    asm volatile(                                                               \
        "mma.sync.aligned.m16n8k16.row.col.f32.f16.f16.f32 "                    \
        "{%0,%1,%2,%3},{%4,%5,%6,%7},{%8,%9},{%0,%1,%2,%3};"                    \
        : "+f"((d)[0]), "+f"((d)[1]), "+f"((d)[2]), "+f"((d)[3])                \
        : "r"((a)[0]), "r"((a)[1]), "r"((a)[2]), "r"((a)[3]),                   \
          "r"((b)[0]), "r"((b)[1]))

#define LDSM4(r0, r1, r2, r3, addr)                                             \
    asm volatile("ldmatrix.sync.aligned.m8n8.x4.shared.b16 {%0,%1,%2,%3},[%4];" \
        : "=r"(r0), "=r"(r1), "=r"(r2), "=r"(r3) : "r"(addr))

#define CP16(dst, src)                                                          \
    asm volatile("cp.async.cg.shared.global [%0], [%1], 16;" ::                 \
                 "r"(dst), "l"(src) : "memory")

#define CPCOMMIT() asm volatile("cp.async.commit_group;" ::: "memory")

// stage layout: [Ah: BM rows][Al: BM rows, TERMS==2 only][Bh: BN rows], 128B rows
template<int BM, int BN, int TERMS>
__device__ __forceinline__ void load_stage_fn(uint32_t base, int tid,
        const __half* __restrict__ Ah, const __half* __restrict__ Al,
        const __half* __restrict__ Bh, int K, int kt) {
#pragma unroll
    for (int i = 0; i < BM * 8 / 256; i++) {
        int cid = tid + i * 256;
        int r = cid >> 3, c = cid & 7;
        CP16(base + r * 128 + ((c ^ (r & 7)) << 4),
             Ah + (size_t)r * K + kt * 64 + c * 8);
    }
    if (TERMS == 2) {
#pragma unroll
        for (int i = 0; i < BM * 8 / 256; i++) {
            int cid = tid + i * 256;
            int r = cid >> 3, c = cid & 7;
            CP16(base + BM * 128 + r * 128 + ((c ^ (r & 7)) << 4),
                 Al + (size_t)r * K + kt * 64 + c * 8);
        }
    }
#pragma unroll
    for (int i = 0; i < BN * 8 / 256; i++) {
        int cid = tid + i * 256;
        int r = cid >> 3, c = cid & 7;
        CP16(base + TERMS * BM * 128 + r * 128 + ((c ^ (r & 7)) << 4),
             Bh + (size_t)r * K + kt * 64 + c * 8);
    }
}

template<int BM, int BN, int TERMS>
__global__ void __launch_bounds__(256, (TERMS == 2 && BN == 128) ? 2 : 3)
fp16_gemm_kernel(
        const __half* __restrict__ Ah, const __half* __restrict__ Al,
        const __half* __restrict__ Bh,
        float* __restrict__ C, __half* __restrict__ Chi, __half* __restrict__ Clo,
        int M, int N, int K, int flags) {
    extern __shared__ __align__(128) char smem[];
    constexpr int ASTAGE = BM * 128;
    constexpr int STAGE  = (TERMS * BM + BN) * 128;
    uint32_t smBase = (uint32_t)__cvta_generic_to_shared(smem);

    const int tid  = threadIdx.x;
    const int lane = tid & 31;
    const int gid  = lane >> 2;
    const int tig  = lane & 3;
    const int warp = tid >> 5;
    constexpr int MT = (BM / 2) / 16;          // 2
    constexpr int NT = (BN / 4) / 8;           // 4 (BN=128) or 2 (64)
    const int wm = warp & 1, wn = warp >> 1;
    const int mBase = wm * (BM / 2);
    const int nBase = wn * (BN / 4);
    const int blockRow = blockIdx.y * BM;
    const int blockCol = blockIdx.x * BN;

    const __half* Ah0 = Ah + (size_t)blockRow * K;
    const __half* Al0 = Al + (size_t)blockRow * K;
    const __half* Bh0 = Bh + (size_t)blockCol * K;

    float acc[MT][NT][4];
#pragma unroll
    for (int i = 0; i < MT; i++)
#pragma unroll
        for (int j = 0; j < NT; j++)
#pragma unroll
            for (int q = 0; q < 4; q++) acc[i][j][q] = 0.f;

    const int ktiles = K / 64;
    const int ksl = ktiles / gridDim.z;
    const int kt0 = ksl * blockIdx.z;

    const int arow = (lane & 7) + ((lane >> 3) & 1) * 8;
    const int acsel = lane >> 4;
    const int nrow = lane & 7;
    const int bcsel = (lane >> 3) & 1;
    const int ntsel = lane >> 4;

    load_stage_fn<BM, BN, TERMS>(smBase, tid, Ah0, Al0, Bh0, K, kt0);
    CPCOMMIT();
    load_stage_fn<BM, BN, TERMS>(smBase + STAGE, tid, Ah0, Al0, Bh0, K, kt0 + 1);
    CPCOMMIT();

    for (int ktl = 0; ktl < ksl; ktl++) {
        asm volatile("cp.async.wait_group 1;" ::: "memory");
        __syncthreads();
        if (ktl + 2 < ksl)
            load_stage_fn<BM, BN, TERMS>(smBase + ((ktl + 2) % 3) * STAGE, tid,
                                         Ah0, Al0, Bh0, K, kt0 + ktl + 2);
        CPCOMMIT();

        uint32_t AhA = smBase + (ktl % 3) * STAGE;
        uint32_t AlA = AhA + ASTAGE;
        uint32_t BhA = AhA + TERMS * ASTAGE;
#pragma unroll
        for (int s = 0; s < 4; s++) {
            const int ck = 2 * s;
            uint32_t bh[NT][2];
#pragma unroll
            for (int np = 0; np < NT / 2; np++) {
                int nt0 = np * 2;
                int r = nBase + (nt0 + ntsel) * 8 + nrow;
                LDSM4(bh[nt0][0], bh[nt0][1], bh[nt0 + 1][0], bh[nt0 + 1][1],
                      BhA + r * 128 + (((ck + bcsel) ^ (r & 7)) << 4));
            }
            // hoist ALL A fragments first, then issue MMAs grouped by term so
            // same-accumulator reuse distance is MT*NT (was NT).
            uint32_t ah[MT][4], al[MT][4];
#pragma unroll
            for (int mt = 0; mt < MT; mt++) {
                int r = mBase + mt * 16 + arow;
                int xo = ((ck + acsel) ^ (r & 7)) << 4;
                LDSM4(ah[mt][0], ah[mt][1], ah[mt][2], ah[mt][3], AhA + r * 128 + xo);
                if (TERMS == 2)
                    LDSM4(al[mt][0], al[mt][1], al[mt][2], al[mt][3], AlA + r * 128 + xo);
            }
#pragma unroll
            for (int mt = 0; mt < MT; mt++)
#pragma unroll
                for (int nt = 0; nt < NT; nt++)
                    MMA_F16F32(acc[mt][nt], ah[mt], bh[nt]);
            if (TERMS == 2) {
#pragma unroll
                for (int mt = 0; mt < MT; mt++)
#pragma unroll
                    for (int nt = 0; nt < NT; nt++)
                        MMA_F16F32(acc[mt][nt], al[mt], bh[nt]);
            }
        }
    }

    // epilogue
    const bool multiZ = (gridDim.z > 1);
#pragma unroll
    for (int mt = 0; mt < MT; mt++) {
#pragma unroll
        for (int nt = 0; nt < NT; nt++) {
            int col = blockCol + nBase + nt * 8 + tig * 2;
            float* a = acc[mt][nt];
#pragma unroll
            for (int hh = 0; hh < 2; hh++) {
                int row = blockRow + mBase + mt * 16 + gid + hh * 8;
                size_t o = (size_t)row * N + col;
                float v0 = a[hh * 2 + 0], v1 = a[hh * 2 + 1];
                if (flags == 2) {
                    float g0 = gelu_tanh(v0), g1 = gelu_tanh(v1);
                    __half h0, l0, h1, l1;
                    split_fp16(g0, h0, l0); split_fp16(g1, h1, l1);
                    Chi[o] = h0; Clo[o] = l0; Chi[o + 1] = h1; Clo[o + 1] = l1;
                } else if (flags == 1) {
                    if (multiZ) { atomicAdd(&C[o], v0); atomicAdd(&C[o + 1], v1); }
                    else        { C[o] += v0; C[o + 1] += v1; }
                } else {
                    C[o] = v0; C[o + 1] = v1;
                }
            }
        }
    }
}

static void launch_fp16(const __half* Ah, const __half* Al, const __half* Bh,
                        float* C, __half* Chi, __half* Clo,
                        int M, int N, int K, int flags, int terms) {
    if (M >= 1024 && N >= 2048) {
        if (terms == 1) {
            constexpr int SMB = 3 * (64 + 128) * 128;
            cudaFuncSetAttribute(fp16_gemm_kernel<64, 128, 1>,
                                 cudaFuncAttributeMaxDynamicSharedMemorySize, SMB);
            dim3 grid(N / 128, M / 64);
            fp16_gemm_kernel<64, 128, 1><<<grid, 256, SMB>>>(Ah, Al, Bh, C, Chi, Clo,
                                                             M, N, K, flags);
        } else {
            constexpr int SMB = 3 * (2 * 64 + 128) * 128;
            cudaFuncSetAttribute(fp16_gemm_kernel<64, 128, 2>,
                                 cudaFuncAttributeMaxDynamicSharedMemorySize, SMB);
            dim3 grid(N / 128, M / 64);
            fp16_gemm_kernel<64, 128, 2><<<grid, 256, SMB>>>(Ah, Al, Bh, C, Chi, Clo,
                                                             M, N, K, flags);
        }
    } else {
        int ks = (flags == 1 && M < 1024 && N <= 1024) ? 4 : 1;
        dim3 grid(N / 64, M / 64, ks);
        if (terms == 1) {
            constexpr int SMB = 3 * (64 + 64) * 128;
            cudaFuncSetAttribute(fp16_gemm_kernel<64, 64, 1>,
                                 cudaFuncAttributeMaxDynamicSharedMemorySize, SMB);
            fp16_gemm_kernel<64, 64, 1><<<grid, 256, SMB>>>(Ah, Al, Bh, C, Chi, Clo,
                                                            M, N, K, flags);
        } else {
            constexpr int SMB = 3 * (2 * 64 + 64) * 128;
            cudaFuncSetAttribute(fp16_gemm_kernel<64, 64, 2>,
                                 cudaFuncAttributeMaxDynamicSharedMemorySize, SMB);
            fp16_gemm_kernel<64, 64, 2><<<grid, 256, SMB>>>(Ah, Al, Bh, C, Chi, Clo,
                                                            M, N, K, flags);
        }
    }
}

// ---------------- SIMT fp32 GEMM (embed only) ----------------
#define BMs 64
#define BNs 64
#define BKK 16
__global__ void gemm_kernel(const float* __restrict__ A, const float* __restrict__ B,
                            const float* __restrict__ bias, float* __restrict__ C,
                            int M, int N, int K, int lda, int ldb, int ldc) {
    __shared__ float As[BKK][BMs + 4];
    __shared__ float Bs[BKK][BNs + 4];
    int tid = threadIdx.y * 16 + threadIdx.x;
    int rowBase = blockIdx.y * BMs;
    int colBase = blockIdx.x * BNs;
    int r0 = threadIdx.y * 4, c0 = threadIdx.x * 4;
    float acc[4][4] = {};
    int aRow = tid >> 2;
    int aK   = (tid & 3) * 4;
    int bRow = tid >> 4;
    int bCol = (tid & 15) * 4;

    for (int kk = 0; kk < K; kk += BKK) {
        {
            int gr = rowBase + aRow;
            float4 v = make_float4(0.f, 0.f, 0.f, 0.f);
            if (gr < M) v = *(const float4*)(A + (size_t)gr * lda + kk + aK);
            As[aK + 0][aRow] = v.x; As[aK + 1][aRow] = v.y;
            As[aK + 2][aRow] = v.z; As[aK + 3][aRow] = v.w;
        }
        {
            int gc = colBase + bCol;
            float4 v = make_float4(0.f, 0.f, 0.f, 0.f);
            if (gc < N) v = *(const float4*)(B + (size_t)(kk + bRow) * ldb + gc);
            Bs[bRow][bCol + 0] = v.x; Bs[bRow][bCol + 1] = v.y;
            Bs[bRow][bCol + 2] = v.z; Bs[bRow][bCol + 3] = v.w;
        }
        __syncthreads();
#pragma unroll
        for (int k = 0; k < BKK; k++) {
            float a[4], bb[4];
#pragma unroll
            for (int i = 0; i < 4; i++) a[i] = As[k][r0 + i];
#pragma unroll
            for (int j = 0; j < 4; j++) bb[j] = Bs[k][c0 + j];
#pragma unroll
            for (int i = 0; i < 4; i++)
#pragma unroll
                for (int j = 0; j < 4; j++) acc[i][j] += a[i] * bb[j];
        }
        __syncthreads();
    }
#pragma unroll
    for (int i = 0; i < 4; i++) {
        int r = rowBase + r0 + i;
        if (r >= M) continue;
#pragma unroll
        for (int j = 0; j < 4; j++) {
            int c = colBase + c0 + j;
            if (c >= N) continue;
            C[(size_t)r * ldc + c] = acc[i][j] + bias[c];
        }
    }
}

// ---------------- attention with fused KV-cache append (hi-only output) -----
__global__ void attn_kernel(const float* __restrict__ qkv, float* __restrict__ Kc,
                            float* __restrict__ Vc,
                            __half* __restrict__ outh,
                            int N, int C, int off) {
    int bh = blockIdx.x; int b = bh / NH, h = bh % NH;
    int n = threadIdx.y, lane = threadIdx.x;
    int t = b * N + n;
    size_t src = (size_t)t * 3 * DMODEL + h * HDIM;
    size_t dst = ((size_t)b * CMAX + off + n) * DMODEL + h * HDIM;
    Kc[dst + lane]      = qkv[src + DMODEL + lane];
    Kc[dst + lane + 32] = qkv[src + DMODEL + lane + 32];
    Vc[dst + lane]      = qkv[src + 2 * DMODEL + lane];
    Vc[dst + lane + 32] = qkv[src + 2 * DMODEL + lane + 32];
    __syncthreads();

    const float* q = qkv + src;
    int lim = n + off;
    float s = -1e30f;
    if (lane < C && lane <= lim) {
        const float* kr = Kc + ((size_t)b * CMAX + lane) * DMODEL + h * HDIM;
        float d = 0.f;
#pragma unroll
        for (int i = 0; i < HDIM; i++) d += q[i] * kr[i];
        s = d * 0.125f;
    }
    float mx = s;
#pragma unroll
    for (int o = 16; o; o >>= 1) mx = fmaxf(mx, __shfl_xor_sync(0xffffffffu, mx, o));
    float p = (lane < C && lane <= lim) ? expf(s - mx) : 0.f;
    float sum = warpSum(p);
    float a0 = 0.f, a1 = 0.f;
    int mmax = min(lim, C - 1);
    for (int m = 0; m <= mmax; m++) {
        float pm = __shfl_sync(0xffffffffu, p, m);
        const float* vr = Vc + ((size_t)b * CMAX + m) * DMODEL + h * HDIM;
        a0 += pm * vr[lane];
        a1 += pm * vr[lane + 32];
    }
    float inv = 1.f / sum;
    size_t i0 = (size_t)t * DMODEL + h * HDIM + lane;
    outh[i0]      = __float2half_rn(a0 * inv);
    outh[i0 + 32] = __float2half_rn(a1 * inv);
}

// ---------------- output assembly ----------------
__global__ void assemble_kernel(float* __restrict__ out) {
    int idx = blockIdx.x * blockDim.x + threadIdx.x;
    int b = idx / 256, t = idx % 256;
    float m;
    if (t < 128) {
        m = 0.5f * (g_last[b * 128 + t] - g_last[(b + 32) * 128 + t]);
    } else {
        int o = t - 128;
        float va = g_no2[b * 128 + o]        * (g_nsg[b * 4 + 3] + EPSF)        + g_nmu[b * 4 + 3];
        float vb = g_no2[(b + 32) * 128 + o] * (g_nsg[(b + 32) * 4 + 3] + EPSF) + g_nmu[(b + 32) * 4 + 3];
        m = 0.5f * (va - vb);
    }
    if (g_ispos[b]) m = fmaxf(m, 0.f);
    out[idx] = m;
}

// ---------------- pointers bundle ----------------
struct DevPtrs {
    float *normed, *anorm, *hdd, *qkv, *Kc, *Vc, *no1, *no2;
    __half *xnh, *xnl, *atth, *h1h, *h1l;
    __half *qkvh, *woh, *w1h, *w2h;
};

// ---------------- full transformer forward ----------------
static void model_fwd_host(const DevPtrs& P, int T, int N, int C, int off,
                           const float* in_tok,
                           const float* W_in, const float* b_in, const float* ln1,
                           const float* ln2, const float* lnf,
                           float* nosel, int selStart, int selStep) {
    dim3 eg((DMODEL + BNs - 1) / BNs, (T + BMs - 1) / BMs), eb(16, 16);
    gemm_kernel<<<eg, eb>>>(in_tok, W_in, b_in, P.hdd, T, DMODEL, PATCH,
                            PATCH, DMODEL, DMODEL);
    for (int l = 0; l < NLAYER; l++) {
        ln_fp16_kernel<<<T, 256>>>(P.hdd, ln1 + (size_t)l * DMODEL, P.xnh, P.xnl);
        launch_fp16(P.xnh, P.xnl, P.qkvh + (size_t)l * 3072 * 1024,
                    P.qkv, nullptr, nullptr, T, 3 * DMODEL, DMODEL, 0, /*terms=*/1);
        float* Kl = P.Kc + (size_t)l * NB * CMAX * DMODEL;
        float* Vl = P.Vc + (size_t)l * NB * CMAX * DMODEL;
        attn_kernel<<<NB * NH, dim3(32, N)>>>(P.qkv, Kl, Vl, P.atth, N, C, off);
        launch_fp16(P.atth, nullptr, P.woh + (size_t)l * 1024 * 1024,
                    P.hdd, nullptr, nullptr, T, DMODEL, DMODEL, 1, /*terms=*/1);
        ln_fp16_kernel<<<T, 256>>>(P.hdd, ln2 + (size_t)l * DMODEL, P.xnh, P.xnl);
        launch_fp16(P.xnh, P.xnl, P.w1h + (size_t)l * 4096 * 1024,
                    nullptr, P.h1h, P.h1l, T, NDFF, DMODEL, 2, /*terms=*/2);
        launch_fp16(P.h1h, P.h1l, P.w2h + (size_t)l * 1024 * 4096,
                    P.hdd, nullptr, nullptr, T, DMODEL, NDFF, 1, /*terms=*/2);
    }
    wout_ln_kernel<<<8, 256>>>(P.hdd, lnf, nosel, selStart, selStep);
}

// ---------------- entry ----------------
extern "C" void kernel_launch(void* const* d_in, const int* in_sizes, int n_in,
                              void* d_out, int out_size) {
    const float* x     = (const float*)d_in[0];
    const float* W_in  = (const float*)d_in[1];
    const float* b_in  = (const float*)d_in[2];
    const float* ln1_s = (const float*)d_in[3];
    const float* Wqkv  = (const float*)d_in[4];
    const float* Wo    = (const float*)d_in[5];
    const float* ln2_s = (const float*)d_in[6];
    const float* W1    = (const float*)d_in[7];
    const float* W2    = (const float*)d_in[8];
    const float* lnf_s = (const float*)d_in[9];
    const float* Wout  = (const float*)d_in[10];
    // d_in[11] = Wqs: provably unused for the median (channel-5) output

    DevPtrs P;
    cudaGetSymbolAddress((void**)&P.normed, g_normed);
    cudaGetSymbolAddress((void**)&P.anorm,  g_anorm);
    cudaGetSymbolAddress((void**)&P.hdd,    g_hdd);
    cudaGetSymbolAddress((void**)&P.qkv,    g_qkv);
    cudaGetSymbolAddress((void**)&P.Kc,     g_Kc);
    cudaGetSymbolAddress((void**)&P.Vc,     g_Vc);
    cudaGetSymbolAddress((void**)&P.no1,    g_no1);
    cudaGetSymbolAddress((void**)&P.no2,    g_no2);
    cudaGetSymbolAddress((void**)&P.xnh,    g_xnh);
    cudaGetSymbolAddress((void**)&P.xnl,    g_xnl);
    cudaGetSymbolAddress((void**)&P.atth,   g_atth);
    cudaGetSymbolAddress((void**)&P.h1h,    g_h1h);
    cudaGetSymbolAddress((void**)&P.h1l,    g_h1l);
    cudaGetSymbolAddress((void**)&P.qkvh,   g_Wqkvh);
    cudaGetSymbolAddress((void**)&P.woh,    g_Woh);
    cudaGetSymbolAddress((void**)&P.w1h,    g_W1h);
    cudaGetSymbolAddress((void**)&P.w2h,    g_W2h);

    // Stage 0: weight transpose + fp16 convert (hi only) + Wout columns
    convT_kernel<<<dim3(3072 / 32, 1024 / 32, NLAYER), dim3(32, 8)>>>(Wqkv, P.qkvh, 1024, 3072);
    convT_kernel<<<dim3(1024 / 32, 1024 / 32, NLAYER), dim3(32, 8)>>>(Wo,   P.woh,  1024, 1024);
    convT_kernel<<<dim3(4096 / 32, 1024 / 32, NLAYER), dim3(32, 8)>>>(W1,   P.w1h,  1024, 4096);
    convT_kernel<<<dim3(1024 / 32, 4096 / 32, NLAYER), dim3(32, 8)>>>(W2,   P.w2h,  4096, 1024);
    wsel_kernel<<<512, 256>>>(Wout);

    // Stage A: running stats + normalization for x and -x (batch 64)
    stats_kernel<<<NB, 32>>>(x);

    // Stage B: prefill (C=16, offset 0)
    model_fwd_host(P, T1, NPATCH, 16, 0, P.normed,
                   W_in, b_in, ln1_s, ln2_s, lnf_s,
                   P.no1, /*selStart=*/15, /*selStep=*/16);

    // Stage C: fused revin + AR stats, then one autoregressive step
    revin_ar_stats_kernel<<<NB, 32>>>();
    model_fwd_host(P, T2, 4, 20, 16, P.anorm,
                   W_in, b_in, ln1_s, ln2_s, lnf_s,
                   P.no2, /*selStart=*/3, /*selStep=*/4);

    // Stage D: combine x / -x, clamp, write [32,256]
    assemble_kernel<<<32, 256>>>((float*)d_out);
}